// round 15
// baseline (speedup 1.0000x reference)
#include <cuda_runtime.h>
#include <cstdint>

#define N_TOK   4096
#define C_DIM   64
#define HW      256
#define E_EXP   16
#define CCAP    384
#define PLANE   (E_EXP * CCAP)             /* 6144 */
#define HALF    ((long long)N_TOK * PLANE) /* 25,165,824 floats */
#define NBIN    32

// ---------------- device scratch (bins reset each replay by k_finish blk 0) --------
__device__ float g_gate[N_TOK];
__device__ int   g_arg[N_TOK];
__device__ float g_psumb[NBIN * E_EXP];   // binned prob sums (bin-major)
__device__ float g_zsumb[NBIN];           // binned lse sums

// =====================================================================
// K1: pure-read pool (R12-proven). grid = 4096 x 512.
// Triggers PDL at block start so k_finish's launch overhead hides here.
// =====================================================================
__global__ void __launch_bounds__(512, 4)
k_pool(const float* __restrict__ X, const float* __restrict__ Wg,
       const float* __restrict__ bg) {
    cudaTriggerProgrammaticLaunchCompletion();   // fire-and-forget; sync is in finish

    const int n    = blockIdx.x;
    const int tid  = threadIdx.x;
    const int w    = tid >> 5;
    const int lane = tid & 31;

    __shared__ float s_ch[C_DIM];
    __shared__ float s_w[C_DIM * E_EXP];

    for (int i = tid; i < C_DIM * E_EXP; i += 512) s_w[i] = Wg[i];

    // coalesced streaming read; warp w owns channels [4w, 4w+4)
    const float4* p = reinterpret_cast<const float4*>(X + (size_t)n * C_DIM * HW)
                      + w * 256;
    float part[4] = {0.f, 0.f, 0.f, 0.f};
#pragma unroll
    for (int k = 0; k < 8; k++) {
        float4 v = __ldcs(p + lane + 32 * k);       // lanes consecutive -> coalesced
        part[k >> 1] += (v.x + v.y) + (v.z + v.w);
    }
#pragma unroll
    for (int c = 0; c < 4; c++) {
        float s = part[c];
#pragma unroll
        for (int off = 16; off; off >>= 1) s += __shfl_xor_sync(0xffffffffu, s, off);
        if (lane == 0) s_ch[4 * w + c] = s * (1.0f / HW);
    }
    __syncthreads();

    if (w == 0) {
        float l = -INFINITY;
        if (lane < E_EXP) {
            float acc = bg[lane];
#pragma unroll
            for (int c = 0; c < C_DIM; c++) acc += s_ch[c] * s_w[c * E_EXP + lane];
            l = acc;
        }
        float mx = l;
#pragma unroll
        for (int off = 16; off; off >>= 1) mx = fmaxf(mx, __shfl_xor_sync(0xffffffffu, mx, off));
        float e = (lane < E_EXP) ? __expf(l - mx) : 0.f;
        float s = e;
#pragma unroll
        for (int off = 16; off; off >>= 1) s += __shfl_xor_sync(0xffffffffu, s, off);
        float prob = e / s;
        float lse  = mx + __logf(s);

        unsigned bal = __ballot_sync(0xffffffffu, l == mx);
        int arg = __ffs(bal) - 1;                   // lowest-index max == jnp argmax
        float gate = __shfl_sync(0xffffffffu, prob, arg);

        const int bin = n & (NBIN - 1);             // spread atomic contention 32x
        if (lane < E_EXP) atomicAdd(&g_psumb[bin * E_EXP + lane], prob);
        if (lane == 0) {
            g_gate[n] = gate;
            g_arg[n]  = arg;
            atomicAdd(&g_zsumb[bin], lse);
        }
    }
}

// =====================================================================
// K2: finish (R12-proven structure) with PDL prelude. grid = 32 x 512.
// Launches under pool's tail; cudaGridDependencySynchronize() blocks
// until pool (and transitively the memset) is complete + visible.
// =====================================================================
__global__ void __launch_bounds__(512)
k_finish(float* __restrict__ out) {
    __shared__ int            s_arg[N_TOK];    // 16 KB
    __shared__ unsigned short s_rank[N_TOK];   //  8 KB
    __shared__ int s_cnt[16][E_EXP + 1];
    __shared__ int s_off[16][E_EXP + 1];
    __shared__ int s_tot[E_EXP];
    __shared__ float s_psum[E_EXP];
    __shared__ float s_z;

    const int bid  = blockIdx.x;
    const int tid  = threadIdx.x;
    const int w    = tid >> 5;
    const int lane = tid & 31;

    // ---- prelude (independent of pool results) ----
    if (lane <= E_EXP) s_cnt[w][lane] = 0;
    if (tid < E_EXP)   s_psum[tid] = 0.f;
    if (tid == 0)      s_z = 0.f;

    // ---- wait for pool completion (memory visible on return) ----
    cudaGridDependencySynchronize();

    // phase 0: bulk coalesced prefetch of g_arg (L2-hot)
    {
        const int4* pa = reinterpret_cast<const int4*>(g_arg);
#pragma unroll
        for (int r = 0; r < 2; r++) {
            int i = tid + r * 512;
            reinterpret_cast<int4*>(s_arg)[i] = pa[i];
        }
    }
    __syncthreads();

    // phase A: per-chunk expert ranks (warp w owns tokens [256w, 256w+256))
#pragma unroll
    for (int g = 0; g < 8; g++) {
        int n = 256 * w + 32 * g + lane;
        int a = s_arg[n];
        unsigned m = __match_any_sync(0xffffffffu, a);
        int prior = s_cnt[w][a];
        __syncwarp();
        if (lane == (int)__ffs(m) - 1) s_cnt[w][a] = prior + __popc(m);
        s_rank[n] = (unsigned short)(prior + __popc(m & ((1u << lane) - 1u)));
        __syncwarp();
    }
    __syncthreads();

    // phase B: exclusive prefix over 16 chunks (warp w = expert w)
    if (lane < 16) {
        int v = s_cnt[lane][w];
        int x = v;
#pragma unroll
        for (int off = 1; off < 16; off <<= 1) {
            int y = __shfl_up_sync(0x0000ffffu, x, off);
            if (lane >= off) x += y;
        }
        s_off[lane][w] = x - v;
        if (lane == 15) s_tot[w] = x;
    }
    __syncthreads();

    // phase C: scatter this block's 128 tokens (one per thread, tid<128)
    if (tid < 128) {
        int n   = 128 * bid + tid;
        int a   = s_arg[n];
        int pos = s_off[n >> 8][a] + (int)s_rank[n];
        if (pos < CCAP) {
            long long off = (long long)n * PLANE + a * CCAP + pos;
            float gate = g_gate[n];                 // L2-hit
            __stcs(out + off, 1.0f);                // dispatch
            __stcs(out + HALF + off, gate);         // combine
        }
    }

    // block 0: scalars + bin reset for next graph replay
    if (bid == 0) {
        {
            float v = g_psumb[tid];                 // 512 = NBIN*E_EXP exactly
            g_psumb[tid] = 0.f;
            atomicAdd(&s_psum[tid & (E_EXP - 1)], v);
            if (tid < NBIN) {
                float z = g_zsumb[tid];
                g_zsumb[tid] = 0.f;
                atomicAdd(&s_z, z);
            }
        }
        __syncthreads();
        if (tid == 0) {
            float aux = 0.f;
#pragma unroll
            for (int e = 0; e < E_EXP; e++) aux += s_psum[e] * (float)s_tot[e];
            const float invN = 1.0f / (float)N_TOK;
            out[2 * HALF]     = s_z * invN;                        // z_loss
            out[2 * HALF + 1] = aux * (float)E_EXP * invN * invN;  // aux_loss
        }
    }
}

// ---------------- launch ----------------
extern "C" void kernel_launch(void* const* d_in, const int* in_sizes, int n_in,
                              void* d_out, int out_size) {
    const float* X  = (const float*)d_in[0];
    const float* Wg = (const float*)d_in[1];
    const float* bg = (const float*)d_in[2];
    float* out = (float*)d_out;

    // driver memset node: pure-write zero-fill of both output planes
    cudaMemsetAsync(out, 0, (size_t)(2 * HALF) * sizeof(float));

    k_pool<<<N_TOK, 512>>>(X, Wg, bg);   // pure-read stream + PDL trigger

    // finish launched with programmatic stream serialization (PDL edge):
    // its launch overhead overlaps pool's tail wave.
    cudaLaunchConfig_t cfg = {};
    cfg.gridDim  = dim3(32, 1, 1);
    cfg.blockDim = dim3(512, 1, 1);
    cfg.dynamicSmemBytes = 0;
    cfg.stream = 0;
    cudaLaunchAttribute attr[1];
    attr[0].id = cudaLaunchAttributeProgrammaticStreamSerialization;
    attr[0].val.programmaticStreamSerializationAllowed = 1;
    cfg.attrs = attr;
    cfg.numAttrs = 1;
    cudaLaunchKernelEx(&cfg, k_finish, out);
}

// round 16
// speedup vs baseline: 1.0399x; 1.0399x over previous
#include <cuda_runtime.h>
#include <cstdint>

#define N_TOK   4096
#define C_DIM   64
#define HW      256
#define E_EXP   16
#define CCAP    384
#define PLANE   (E_EXP * CCAP)             /* 6144 */
#define HALF    ((long long)N_TOK * PLANE) /* 25,165,824 floats */
#define NBIN    32

// ---------------- device scratch (bins reset each replay by k_finish blk 0) --------
__device__ float g_gate[N_TOK];
__device__ int   g_arg[N_TOK];
__device__ float g_psumb[NBIN * E_EXP];   // binned prob sums (bin-major)
__device__ float g_zsumb[NBIN];           // binned lse sums

// =====================================================================
// K1: pure-read pool with distributed gate matvec. grid = 4096 x 512.
// Warp w owns channels [4w, 4w+4): loads X, reduces, computes its 16
// partial logits with register-resident W. Warp 0 only sums 16 partials
// and does the softmax -> tiny post-barrier tail.
// =====================================================================
__global__ void __launch_bounds__(512, 4)
k_pool(const float* __restrict__ X, const float* __restrict__ Wg,
       const float* __restrict__ bg) {
    const int n    = blockIdx.x;
    const int tid  = threadIdx.x;
    const int w    = tid >> 5;
    const int lane = tid & 31;

    __shared__ float s_part[16][E_EXP];   // per-warp partial logits

    // preload this warp's W slice into registers (lanes 0-15 only)
    float wreg0 = 0.f, wreg1 = 0.f, wreg2 = 0.f, wreg3 = 0.f;
    if (lane < E_EXP) {
        const float* wr = Wg + (4 * w) * E_EXP + lane;
        wreg0 = wr[0 * E_EXP];
        wreg1 = wr[1 * E_EXP];
        wreg2 = wr[2 * E_EXP];
        wreg3 = wr[3 * E_EXP];
    }

    // coalesced streaming read; warp w owns channels [4w, 4w+4)
    const float4* p = reinterpret_cast<const float4*>(X + (size_t)n * C_DIM * HW)
                      + w * 256;
    float part[4] = {0.f, 0.f, 0.f, 0.f};
#pragma unroll
    for (int k = 0; k < 8; k++) {
        float4 v = __ldcs(p + lane + 32 * k);       // lanes consecutive -> coalesced
        part[k >> 1] += (v.x + v.y) + (v.z + v.w);
    }

    // butterfly reduce -> ALL lanes hold each channel mean
#pragma unroll
    for (int c = 0; c < 4; c++) {
        float s = part[c];
#pragma unroll
        for (int off = 16; off; off >>= 1) s += __shfl_xor_sync(0xffffffffu, s, off);
        part[c] = s * (1.0f / HW);
    }

    // lanes 0-15: this warp's partial logit for expert `lane`
    if (lane < E_EXP) {
        float acc = part[0] * wreg0 + part[1] * wreg1
                  + part[2] * wreg2 + part[3] * wreg3;
        s_part[w][lane] = acc;
    }
    __syncthreads();

    // warp 0: final logits (16 conflict-free LDS) + softmax + argmax
    if (w == 0) {
        float l = -INFINITY;
        if (lane < E_EXP) {
            float acc = bg[lane];
#pragma unroll
            for (int ww = 0; ww < 16; ww++) acc += s_part[ww][lane];
            l = acc;
        }
        float mx = l;
#pragma unroll
        for (int off = 16; off; off >>= 1) mx = fmaxf(mx, __shfl_xor_sync(0xffffffffu, mx, off));
        float e = (lane < E_EXP) ? __expf(l - mx) : 0.f;
        float s = e;
#pragma unroll
        for (int off = 16; off; off >>= 1) s += __shfl_xor_sync(0xffffffffu, s, off);
        float prob = e / s;
        float lse  = mx + __logf(s);

        unsigned bal = __ballot_sync(0xffffffffu, l == mx);
        int arg = __ffs(bal) - 1;                   // lowest-index max == jnp argmax
        float gate = __shfl_sync(0xffffffffu, prob, arg);

        const int bin = n & (NBIN - 1);             // spread atomic contention 32x
        if (lane < E_EXP) atomicAdd(&g_psumb[bin * E_EXP + lane], prob);
        if (lane == 0) {
            g_gate[n] = gate;
            g_arg[n]  = arg;
            atomicAdd(&g_zsumb[bin], lse);
        }
    }
}

// =====================================================================
// K2: finish (exact R12 structure). grid = 32 x 512. Replicated scan,
// block b scatters tokens [128b, 128b+128). Block 0 scalars + bin reset.
// =====================================================================
__global__ void __launch_bounds__(512)
k_finish(float* __restrict__ out) {
    __shared__ int            s_arg[N_TOK];    // 16 KB
    __shared__ unsigned short s_rank[N_TOK];   //  8 KB
    __shared__ int s_cnt[16][E_EXP + 1];
    __shared__ int s_off[16][E_EXP + 1];
    __shared__ int s_tot[E_EXP];

    const int bid  = blockIdx.x;
    const int tid  = threadIdx.x;
    const int w    = tid >> 5;
    const int lane = tid & 31;

    // phase 0: bulk coalesced prefetch of g_arg (L2-hot, read-only)
    {
        const int4* pa = reinterpret_cast<const int4*>(g_arg);
#pragma unroll
        for (int r = 0; r < 2; r++) {
            int i = tid + r * 512;
            reinterpret_cast<int4*>(s_arg)[i] = pa[i];
        }
    }
    __syncthreads();

    // phase A: per-chunk expert ranks (warp w owns tokens [256w, 256w+256))
    if (lane <= E_EXP) s_cnt[w][lane] = 0;
    __syncwarp();
#pragma unroll
    for (int g = 0; g < 8; g++) {
        int n = 256 * w + 32 * g + lane;
        int a = s_arg[n];
        unsigned m = __match_any_sync(0xffffffffu, a);
        int prior = s_cnt[w][a];
        __syncwarp();
        if (lane == (int)__ffs(m) - 1) s_cnt[w][a] = prior + __popc(m);
        s_rank[n] = (unsigned short)(prior + __popc(m & ((1u << lane) - 1u)));
        __syncwarp();
    }
    __syncthreads();

    // phase B: exclusive prefix over 16 chunks (warp w = expert w)
    if (lane < 16) {
        int v = s_cnt[lane][w];
        int x = v;
#pragma unroll
        for (int off = 1; off < 16; off <<= 1) {
            int y = __shfl_up_sync(0x0000ffffu, x, off);
            if (lane >= off) x += y;
        }
        s_off[lane][w] = x - v;
        if (lane == 15) s_tot[w] = x;
    }
    __syncthreads();

    // phase C: scatter this block's 128 tokens (one per thread, tid<128)
    if (tid < 128) {
        int n   = 128 * bid + tid;
        int a   = s_arg[n];
        int pos = s_off[n >> 8][a] + (int)s_rank[n];
        if (pos < CCAP) {
            long long off = (long long)n * PLANE + a * CCAP + pos;
            float gate = g_gate[n];                 // L2-hit
            __stcs(out + off, 1.0f);                // dispatch
            __stcs(out + HALF + off, gate);         // combine
        }
    }

    // block 0: scalars + bin reset for next graph replay
    if (bid == 0) {
        __shared__ float s_psum[E_EXP];
        __shared__ float s_z;
        if (tid < E_EXP) s_psum[tid] = 0.f;
        if (tid == 0)    s_z = 0.f;
        __syncthreads();
        {
            float v = g_psumb[tid];                 // 512 = NBIN*E_EXP exactly
            g_psumb[tid] = 0.f;
            atomicAdd(&s_psum[tid & (E_EXP - 1)], v);
            if (tid < NBIN) {
                float z = g_zsumb[tid];
                g_zsumb[tid] = 0.f;
                atomicAdd(&s_z, z);
            }
        }
        __syncthreads();
        if (tid == 0) {
            float aux = 0.f;
#pragma unroll
            for (int e = 0; e < E_EXP; e++) aux += s_psum[e] * (float)s_tot[e];
            const float invN = 1.0f / (float)N_TOK;
            out[2 * HALF]     = s_z * invN;                        // z_loss
            out[2 * HALF + 1] = aux * (float)E_EXP * invN * invN;  // aux_loss
        }
    }
}

// ---------------- launch ----------------
extern "C" void kernel_launch(void* const* d_in, const int* in_sizes, int n_in,
                              void* d_out, int out_size) {
    const float* X  = (const float*)d_in[0];
    const float* Wg = (const float*)d_in[1];
    const float* bg = (const float*)d_in[2];
    float* out = (float*)d_out;

    // driver memset node: pure-write zero-fill of both output planes
    cudaMemsetAsync(out, 0, (size_t)(2 * HALF) * sizeof(float));

    k_pool<<<N_TOK, 512>>>(X, Wg, bg);   // pure-read stream, distributed matvec
    k_finish<<<32, 512>>>(out);          // replicated scan + parallel scatter
}